// round 7
// baseline (speedup 1.0000x reference)
#include <cuda_runtime.h>
#include <cstdint>

// HarmonicPolynomialR3Generator — R7: 8 points/thread (4 f32x2 pairs).
//  Each cob LDS+pack feeds 4 pairs (8 points): cob l1tex inst/pt halves vs R6.
//  Copy path loads ull (2 points per LDS.64). Otherwise R6 structure:
//  per-stage coalesced copy windows, conflict-free exchange, J=4 k-split.
//  smem 76.7KB/CTA, 128 thr, 3 CTAs/SM.

typedef unsigned long long ull;

__device__ __forceinline__ ull ffma2(ull a, ull b, ull c) {
    ull d; asm("fma.rn.f32x2 %0, %1, %2, %3;" : "=l"(d) : "l"(a), "l"(b), "l"(c)); return d;
}
__device__ __forceinline__ ull fmul2(ull a, ull b) {
    ull d; asm("mul.rn.f32x2 %0, %1, %2;" : "=l"(d) : "l"(a), "l"(b)); return d;
}
__device__ __forceinline__ ull pack2(float lo, float hi) {
    ull d; asm("mov.b64 %0, {%1, %2};" : "=l"(d) : "f"(lo), "f"(hi)); return d;
}

#define BLOCK 128
#define SLOTS 32
#define TILE  256      // 32 slots * 8 points

// cob smem (float units), [3PL][CS] k-major per-j slots (as R5/R6).
#define OFF2   16    // PL=3,  TM=2, SLOTW=2, CS=8
#define OFF3   88    // PL=5,  TM=2, SLOTW=2, CS=8
#define OFF4   208   // PL=7,  TM=4, SLOTW=4, CS=16
#define OFF5   544   // PL=9,  TM=4, SLOTW=4, CS=16
#define OFF6   976   // PL=11, TM=4, SLOTW=4, CS=16
#define OFF7   1504  // PL=13, TM=4, SLOTW=4, CS=16
#define OFF8   2128  // PL=15, TM=6, SLOTW=8, CS=32
#define OFF9   3568  // PL=17, TM=6, SLOTW=8, CS=32
#define OFF10  5200  // PL=19, TM=6, SLOTW=8, CS=32
#define COB_F  7024

// exchange per slot (ull): phase0 pairs p at p*22 (0..87), phase1 at 88+p*22,
// header f1 at 176 + p*3. Stride 190: slot float-stride 380 ≡ 28 mod 32 ->
// 8 warp slots land on disjoint bank quads.
#define EXS    190
#define PH0    0
#define PH1    88
#define HDR    176
#define EX_ULL (SLOTS * EXS)
#define SMEM_BYTES (COB_F * 4 + EX_ULL * 8)   // 28096 + 48640 = 76736

template <int PL, int TM, int SLOTW>
__device__ __forceinline__ void load_cob(const float* __restrict__ c, float* __restrict__ dst, int tid) {
    constexpr int NK = PL + 2;
    constexpr int M = 3 * PL;
    constexpr int CS = 4 * SLOTW;
    for (int e = tid; e < M * CS; e += BLOCK) {
        int m = e / CS;
        int r = e - m * CS;
        int jj = r / SLOTW;
        int t = r - jj * SLOTW;
        int k = jj * TM + t;
        dst[e] = (t < TM && k < NK) ? c[k * M + m] : 0.0f;
    }
}

// Accumulate one prev index i (3 m's) into TM accumulators x 4 pairs.
template <int TM, int CS, bool FIRST>
__device__ __forceinline__ void acc_i(const float* __restrict__ col0,
                                      const ull pv[4],
                                      const ull fx[4], const ull fy[4], const ull fz[4],
                                      ull acc[4][TM]) {
#pragma unroll
    for (int c = 0; c < 3; ++c) {
        ull g[4];
#pragma unroll
        for (int p = 0; p < 4; ++p) {
            const ull f = (c == 0) ? fx[p] : (c == 1) ? fy[p] : fz[p];
            g[p] = fmul2(pv[p], f);
        }
        const float* col = col0 + c * CS;
        ull pk[TM];
        if constexpr (TM == 2) {
            float2 v = *reinterpret_cast<const float2*>(col);
            pk[0] = pack2(v.x, v.x); pk[1] = pack2(v.y, v.y);
        } else if constexpr (TM == 4) {
            float4 v = *reinterpret_cast<const float4*>(col);
            pk[0] = pack2(v.x, v.x); pk[1] = pack2(v.y, v.y);
            pk[2] = pack2(v.z, v.z); pk[3] = pack2(v.w, v.w);
        } else {
            float4 v = *reinterpret_cast<const float4*>(col);
            float2 w = *reinterpret_cast<const float2*>(col + 4);
            pk[0] = pack2(v.x, v.x); pk[1] = pack2(v.y, v.y);
            pk[2] = pack2(v.z, v.z); pk[3] = pack2(v.w, v.w);
            pk[4] = pack2(w.x, w.x); pk[5] = pack2(w.y, w.y);
        }
#pragma unroll
        for (int t = 0; t < TM; ++t) {
#pragma unroll
            for (int p = 0; p < 4; ++p) {
                if (FIRST && c == 0) acc[p][t] = fmul2(pk[t], g[p]);
                else                 acc[p][t] = ffma2(pk[t], g[p], acc[p][t]);
            }
        }
    }
}

// Generic stage (l >= 3): prev from exchange (4 pairs), outputs to exchange.
template <int PL, int TM, int SLOTW>
__device__ __forceinline__ void stage7(const float* __restrict__ cb, const int j,
                                       const ull fx[4], const ull fy[4], const ull fz[4],
                                       const ull* __restrict__ in0, ull* __restrict__ out0) {
    constexpr int NK = PL + 2;
    constexpr int CS = 4 * SLOTW;
    ull acc[4][TM];
    const float* cbj = cb + j * SLOTW;

    {   // i = 0,1
        ulonglong2 q[4];
#pragma unroll
        for (int p = 0; p < 4; ++p) q[p] = *reinterpret_cast<const ulonglong2*>(in0 + p * 22);
        ull pv[4];
#pragma unroll
        for (int p = 0; p < 4; ++p) pv[p] = q[p].x;
        acc_i<TM, CS, true>(cbj, pv, fx, fy, fz, acc);
#pragma unroll
        for (int p = 0; p < 4; ++p) pv[p] = q[p].y;
        acc_i<TM, CS, false>(cbj + 3 * CS, pv, fx, fy, fz, acc);
    }
#pragma unroll
    for (int ii = 2; ii + 1 < PL; ii += 2) {
        ulonglong2 q[4];
#pragma unroll
        for (int p = 0; p < 4; ++p) q[p] = *reinterpret_cast<const ulonglong2*>(in0 + p * 22 + ii);
        ull pv[4];
#pragma unroll
        for (int p = 0; p < 4; ++p) pv[p] = q[p].x;
        acc_i<TM, CS, false>(cbj + 3 * ii * CS, pv, fx, fy, fz, acc);
#pragma unroll
        for (int p = 0; p < 4; ++p) pv[p] = q[p].y;
        acc_i<TM, CS, false>(cbj + 3 * (ii + 1) * CS, pv, fx, fy, fz, acc);
    }
    {   // tail i = PL-1 (PL odd)
        ull pv[4];
#pragma unroll
        for (int p = 0; p < 4; ++p) pv[p] = in0[p * 22 + PL - 1];
        acc_i<TM, CS, false>(cbj + 3 * (PL - 1) * CS, pv, fx, fy, fz, acc);
    }
#pragma unroll
    for (int t = 0; t < TM; ++t) {
        const int k = j * TM + t;
        if (k < NK) {
#pragma unroll
            for (int p = 0; p < 4; ++p) out0[p * 22 + k] = acc[p][t];
        }
    }
}

// Copy one stage's outputs (ull = 2 points) from exchange to gmem.
template <int NK, int OUTOFF, int POFF>
__device__ __forceinline__ void copy_stage(const ull* __restrict__ exu,
                                           float* __restrict__ out,
                                           int base, int rem, int tid) {
#pragma unroll
    for (int i = 0; i < NK; ++i) {        // 128 pairs * NK elements / 128 threads
        int e = tid + i * BLOCK;
        int q = e / NK;                   // pair index 0..127
        int k = e - q * NK;
        int slot = q & 31;
        int p = q >> 5;                   // 0..3
        ull v = exu[slot * EXS + POFF + p * 22 + k];
        float lo, hi;
        asm("mov.b64 {%0, %1}, %2;" : "=f"(lo), "=f"(hi) : "l"(v));
        int ptlo = slot + 64 * p;
        int pthi = ptlo + 32;
        if (ptlo < rem) __stcs(out + (size_t)(base + ptlo) * 121 + OUTOFF + k, lo);
        if (pthi < rem) __stcs(out + (size_t)(base + pthi) * 121 + OUTOFF + k, hi);
    }
}

__device__ __forceinline__ void copy_hdr(const ull* __restrict__ exu,
                                         float* __restrict__ out,
                                         int base, int rem, int tid) {
#pragma unroll
    for (int i = 0; i < 4; ++i) {         // 128 pairs * 4 k / 128 threads
        int e = tid + i * BLOCK;
        int q = e >> 2;
        int k = e & 3;
        int slot = q & 31;
        int p = q >> 5;
        float lo = 1.0f, hi = 1.0f;
        if (k != 0) {
            ull v = exu[slot * EXS + HDR + p * 3 + (k - 1)];
            asm("mov.b64 {%0, %1}, %2;" : "=f"(lo), "=f"(hi) : "l"(v));
        }
        int ptlo = slot + 64 * p;
        int pthi = ptlo + 32;
        if (ptlo < rem) __stcs(out + (size_t)(base + ptlo) * 121 + k, lo);
        if (pthi < rem) __stcs(out + (size_t)(base + pthi) * 121 + k, hi);
    }
}

__global__ void __launch_bounds__(BLOCK, 3)
harmonic_kernel(const float* __restrict__ pts,
                const float* __restrict__ c1, const float* __restrict__ c2,
                const float* __restrict__ c3, const float* __restrict__ c4,
                const float* __restrict__ c5, const float* __restrict__ c6,
                const float* __restrict__ c7, const float* __restrict__ c8,
                const float* __restrict__ c9, const float* __restrict__ c10,
                float* __restrict__ out, int N) {
    extern __shared__ float dynf[];
    float* scob = dynf;
    ull* ex = reinterpret_cast<ull*>(dynf + COB_F);

    const int tid = threadIdx.x;
    const int slot = tid >> 2;
    const int j = tid & 3;

    if (tid < 16) scob[tid] = (tid < 9) ? c1[tid] : 0.0f;
    load_cob<3, 2, 2>(c2, scob + OFF2, tid);
    load_cob<5, 2, 2>(c3, scob + OFF3, tid);
    load_cob<7, 4, 4>(c4, scob + OFF4, tid);
    load_cob<9, 4, 4>(c5, scob + OFF5, tid);
    load_cob<11, 4, 4>(c6, scob + OFF6, tid);
    load_cob<13, 4, 4>(c7, scob + OFF7, tid);
    load_cob<15, 6, 8>(c8, scob + OFF8, tid);
    load_cob<17, 6, 8>(c9, scob + OFF9, tid);
    load_cob<19, 6, 8>(c10, scob + OFF10, tid);
    __syncthreads();

    const int base = blockIdx.x * TILE;
    int rem = N - base; if (rem > TILE) rem = TILE;

    // 8 points: pair p covers (slot + 64p, slot + 64p + 32)
    ull px[4], py[4], pz[4];
#pragma unroll
    for (int p = 0; p < 4; ++p) {
        int plo = base + slot + 64 * p;
        int phi = plo + 32;
        float xl = 0.f, yl = 0.f, zl = 0.f, xh = 0.f, yh = 0.f, zh = 0.f;
        if (plo < N) { xl = pts[3 * plo]; yl = pts[3 * plo + 1]; zl = pts[3 * plo + 2]; }
        if (phi < N) { xh = pts[3 * phi]; yh = pts[3 * phi + 1]; zh = pts[3 * phi + 2]; }
        px[p] = pack2(xl, xh); py[p] = pack2(yl, yh); pz[p] = pack2(zl, zh);
    }

    ull k0 = pack2(scob[0], scob[0]), k1 = pack2(scob[1], scob[1]), k2 = pack2(scob[2], scob[2]);
    ull k3 = pack2(scob[3], scob[3]), k4 = pack2(scob[4], scob[4]), k5 = pack2(scob[5], scob[5]);
    ull k6 = pack2(scob[6], scob[6]), k7 = pack2(scob[7], scob[7]), k8 = pack2(scob[8], scob[8]);

    ull fx[4], fy[4], fz[4];
#pragma unroll
    for (int p = 0; p < 4; ++p) {
        fx[p] = ffma2(k0, px[p], ffma2(k1, py[p], fmul2(k2, pz[p])));
        fy[p] = ffma2(k3, px[p], ffma2(k4, py[p], fmul2(k5, pz[p])));
        fz[p] = ffma2(k6, px[p], ffma2(k7, py[p], fmul2(k8, pz[p])));
    }

    ull* es = ex + slot * EXS;
    if (j == 0) {
#pragma unroll
        for (int p = 0; p < 4; ++p) {
            es[HDR + p * 3 + 0] = fx[p];
            es[HDR + p * 3 + 1] = fy[p];
            es[HDR + p * 3 + 2] = fz[p];
        }
    }

    // ---- stage l=2 (prev = f1 in registers) -> PH0 ----
    {
        ull acc[4][2];
        const float* cbj = scob + OFF2 + j * 2;
        acc_i<2, 8, true >(cbj,      fx, fx, fy, fz, acc);
        acc_i<2, 8, false>(cbj + 24, fy, fx, fy, fz, acc);
        acc_i<2, 8, false>(cbj + 48, fz, fx, fy, fz, acc);
#pragma unroll
        for (int t = 0; t < 2; ++t) {
            int k = j * 2 + t;
            if (k < 5) {
#pragma unroll
                for (int p = 0; p < 4; ++p) es[PH0 + p * 22 + k] = acc[p][t];
            }
        }
    }
    __syncthreads();

    copy_hdr(ex, out, base, rem, tid);
    copy_stage<5, 4, PH0>(ex, out, base, rem, tid);
    stage7<5, 2, 2>(scob + OFF3, j, fx, fy, fz, es + PH0, es + PH1);
    __syncthreads();

    copy_stage<7, 9, PH1>(ex, out, base, rem, tid);
    stage7<7, 4, 4>(scob + OFF4, j, fx, fy, fz, es + PH1, es + PH0);
    __syncthreads();

    copy_stage<9, 16, PH0>(ex, out, base, rem, tid);
    stage7<9, 4, 4>(scob + OFF5, j, fx, fy, fz, es + PH0, es + PH1);
    __syncthreads();

    copy_stage<11, 25, PH1>(ex, out, base, rem, tid);
    stage7<11, 4, 4>(scob + OFF6, j, fx, fy, fz, es + PH1, es + PH0);
    __syncthreads();

    copy_stage<13, 36, PH0>(ex, out, base, rem, tid);
    stage7<13, 4, 4>(scob + OFF7, j, fx, fy, fz, es + PH0, es + PH1);
    __syncthreads();

    copy_stage<15, 49, PH1>(ex, out, base, rem, tid);
    stage7<15, 6, 8>(scob + OFF8, j, fx, fy, fz, es + PH1, es + PH0);
    __syncthreads();

    copy_stage<17, 64, PH0>(ex, out, base, rem, tid);
    stage7<17, 6, 8>(scob + OFF9, j, fx, fy, fz, es + PH0, es + PH1);
    __syncthreads();

    copy_stage<19, 81, PH1>(ex, out, base, rem, tid);
    stage7<19, 6, 8>(scob + OFF10, j, fx, fy, fz, es + PH1, es + PH0);
    __syncthreads();

    copy_stage<21, 100, PH0>(ex, out, base, rem, tid);
}

extern "C" void kernel_launch(void* const* d_in, const int* in_sizes, int n_in,
                              void* d_out, int out_size) {
    const float* points = (const float*)d_in[0];
    const int N = in_sizes[0] / 3;
    float* out = (float*)d_out;

    cudaFuncSetAttribute(harmonic_kernel,
                         cudaFuncAttributeMaxDynamicSharedMemorySize, SMEM_BYTES);

    const int grid = (N + TILE - 1) / TILE;
    harmonic_kernel<<<grid, BLOCK, SMEM_BYTES>>>(
        points,
        (const float*)d_in[1], (const float*)d_in[2], (const float*)d_in[3],
        (const float*)d_in[4], (const float*)d_in[5], (const float*)d_in[6],
        (const float*)d_in[7], (const float*)d_in[8], (const float*)d_in[9],
        (const float*)d_in[10],
        out, N);
}